// round 13
// baseline (speedup 1.0000x reference)
#include <cuda_runtime.h>
#include <cstdint>
#include <cstddef>

#define B_  2048
#define T_  256
#define D_  42
#define H_  64

typedef unsigned long long ull;

// 512MB scratch: gate-packed layer-0 preactivations, {(i,f),(g,o)} per (t,b,j)
__device__ ulonglong2 g_gx0[(size_t)B_ * T_ * H_];

// ---------------------------------------------------------------- helpers ---
__device__ __forceinline__ void fma2(ull& d, ull a, ull b) {
    asm("fma.rn.f32x2 %0, %1, %2, %0;" : "+l"(d) : "l"(a), "l"(b));
}
__device__ __forceinline__ void add2(ull& d, ull a) {
    asm("add.rn.f32x2 %0, %0, %1;" : "+l"(d) : "l"(a));
}
__device__ __forceinline__ ull dupf(float v) {
    unsigned r = __float_as_uint(v);
    ull d; asm("mov.b64 %0, {%1, %1};" : "=l"(d) : "r"(r));
    return d;
}
__device__ __forceinline__ ull dup2(float v) {
    ull u = (ull)__float_as_uint(v); return u | (u << 32);
}
__device__ __forceinline__ ull pack2(float lo, float hi) {
    return (ull)__float_as_uint(lo) | ((ull)__float_as_uint(hi) << 32);
}
__device__ __forceinline__ float lo32(ull u) { return __uint_as_float((unsigned)u); }
__device__ __forceinline__ float hi32(ull u) { return __uint_as_float((unsigned)(u >> 32)); }
__device__ __forceinline__ float sigf(float x)   { return __fdividef(1.0f, 1.0f + __expf(-x)); }
__device__ __forceinline__ float tanhf_(float x) { float e = __expf(2.0f * x); return 1.0f - __fdividef(2.0f, e + 1.0f); }

// ============================================================================
// Prepass: gx0[t][b][j] = x[b,t,:] . W_ih0^T + b_ih0 + b_hh0   (gate-packed)
// ============================================================================
#define PPX      34
#define PP_SMEM  (D_ * H_ * 16 + D_ * PPX * 8)  // 54432 B

__global__ void __launch_bounds__(256, 2)
gx0_prepass(const float* __restrict__ x,
            const float* __restrict__ Wih0,
            const float* __restrict__ bih0,
            const float* __restrict__ bhh0)
{
    extern __shared__ char sm[];
    ulonglong2* Wp = (ulonglong2*)sm;            // [d*64 + j] {(i,f),(g,o)}
    ull*        xd = (ull*)(sm + D_ * H_ * 16);  // [d*PPX + row] duplicated x

    const int tid  = threadIdx.x;
    const int j    = tid & 63;
    const int slot = tid >> 6;
    const int r0   = slot * 8;
    const size_t bt0 = (size_t)blockIdx.x * 32;

    for (int idx = tid; idx < D_ * H_; idx += 256) {
        int d = idx >> 6, jj = idx & 63;
        Wp[idx] = make_ulonglong2(
            pack2(Wih0[(jj      ) * D_ + d], Wih0[(jj +  64) * D_ + d]),
            pack2(Wih0[(jj + 128) * D_ + d], Wih0[(jj + 192) * D_ + d]));
    }
    for (int idx = tid; idx < 32 * D_; idx += 256) {
        int r = idx / D_, d = idx - r * D_;
        xd[d * PPX + r] = dup2(x[(bt0 + r) * D_ + d]);
    }
    const ull bif = pack2(bih0[j      ] + bhh0[j      ], bih0[j +  64] + bhh0[j +  64]);
    const ull bgo = pack2(bih0[j + 128] + bhh0[j + 128], bih0[j + 192] + bhh0[j + 192]);
    __syncthreads();

    ull aif[8], ago[8];
    #pragma unroll
    for (int r = 0; r < 8; r++) { aif[r] = bif; ago[r] = bgo; }

    #pragma unroll 6
    for (int d = 0; d < D_; d++) {
        ulonglong2 w = Wp[d * 64 + j];
        const ull* xr = &xd[d * PPX + r0];
        ulonglong2 xA = *(const ulonglong2*)&xr[0];
        ulonglong2 xB = *(const ulonglong2*)&xr[2];
        ulonglong2 xC = *(const ulonglong2*)&xr[4];
        ulonglong2 xD = *(const ulonglong2*)&xr[6];
        fma2(aif[0], w.x, xA.x); fma2(ago[0], w.y, xA.x);
        fma2(aif[1], w.x, xA.y); fma2(ago[1], w.y, xA.y);
        fma2(aif[2], w.x, xB.x); fma2(ago[2], w.y, xB.x);
        fma2(aif[3], w.x, xB.y); fma2(ago[3], w.y, xB.y);
        fma2(aif[4], w.x, xC.x); fma2(ago[4], w.y, xC.x);
        fma2(aif[5], w.x, xC.y); fma2(ago[5], w.y, xC.y);
        fma2(aif[6], w.x, xD.x); fma2(ago[6], w.y, xD.x);
        fma2(aif[7], w.x, xD.y); fma2(ago[7], w.y, xD.y);
    }
    #pragma unroll
    for (int r = 0; r < 8; r++) {
        size_t bt = bt0 + r0 + r;
        size_t b  = bt / T_;
        size_t t  = bt - b * T_;
        g_gx0[(t * B_ + b) * H_ + j] = make_ulonglong2(aif[r], ago[r]);
    }
}

// ============================================================================
// Recurrent kernel: 128 blocks x 16 rows, 256 threads (8 warps).
// Warp bits: jhi = w&1 (j = jhi*32 + lane), rq = (w>>1)&1 (8 rows),
//            kh = w>>2 (k-half: 32 k).
// SYMMETRIC MERGE: kh0 owns rows ro..ro+3, kh1 owns ro+4..ro+7. Each side
// inits its owned rows with gx/bias, publishes the non-owned partials, then
// merges + cell-updates + writes h for its own 4 rows — MUFU tail spread
// across all 8 warps (2/SMSP) instead of serialized on kh0.
// ============================================================================
#define HP        20                                     // h pitch in floats
#define HBUF      (64 * HP)                              // 1280 floats / buffer
#define SCR_OFF   (3 * 64 * 64 * 16 + 3 * HBUF * 4)      // 211968
#define SMEM_REC  (SCR_OFF + 16 * 128 * 8)               // + 16384 = 228352 B

__global__ void __launch_bounds__(256, 1)
lstm_rec(const float* __restrict__ Whh0,
         const float* __restrict__ Wih1,
         const float* __restrict__ Whh1,
         const float* __restrict__ bih1,
         const float* __restrict__ bhh1,
         const float* __restrict__ Wfc,
         const float* __restrict__ bfc,
         float* __restrict__ out)
{
    extern __shared__ char sm[];
    ulonglong2* W0p  = (ulonglong2*)sm;          // [k*64 + j], 64KB
    ulonglong2* W1ip = W0p  + 64 * 64;           // 64KB
    ulonglong2* W1hp = W1ip + 64 * 64;           // 64KB
    float*      h0d  = (float*)(W1hp + 64 * 64); // 2 buffers of HBUF
    float*      h1d  = h0d + 2 * HBUF;           // 1 buffer
    ull*        scr  = (ull*)(sm + SCR_OFF);     // [16][128] partials

    const int tid  = threadIdx.x;
    const int lane = tid & 31;
    const int wrp  = tid >> 5;                   // 0..7
    const int jhi  = wrp & 1;
    const int rq   = (wrp >> 1) & 1;             // 0..1 (8 rows each)
    const int kh   = wrp >> 2;                   // 0..1 (32 k each)
    const int j    = jhi * 32 + lane;
    const int base = blockIdx.x * 16;
    const int ro   = rq * 8;
    const int kb   = kh * 32;                    // k-range start
    const int rown = ro + kh * 4;                // first of this thread's 4 OWNED rows
    const int tl   = tid & 127;                  // partner-pair index
    // scratch slots: region A (kh0's published rows 4-7) = m 0..7,
    //                region B (kh1's published rows 0-3) = m 8..15
    const int pubm = kh ? 8 : 0;                 // where I publish
    const int rdm  = kh ? 0 : 8;                 // where I read partner partials

    for (int idx = tid; idx < 64 * 64; idx += 256) {
        int k = idx >> 6, jj = idx & 63;
        W0p[idx]  = make_ulonglong2(
            pack2(Whh0[(jj      ) * 64 + k], Whh0[(jj +  64) * 64 + k]),
            pack2(Whh0[(jj + 128) * 64 + k], Whh0[(jj + 192) * 64 + k]));
        W1ip[idx] = make_ulonglong2(
            pack2(Wih1[(jj      ) * 64 + k], Wih1[(jj +  64) * 64 + k]),
            pack2(Wih1[(jj + 128) * 64 + k], Wih1[(jj + 192) * 64 + k]));
        W1hp[idx] = make_ulonglong2(
            pack2(Whh1[(jj      ) * 64 + k], Whh1[(jj +  64) * 64 + k]),
            pack2(Whh1[(jj + 128) * 64 + k], Whh1[(jj + 192) * 64 + k]));
    }
    const ull b1if = pack2(bih1[j      ] + bhh1[j      ], bih1[j +  64] + bhh1[j +  64]);
    const ull b1go = pack2(bih1[j + 128] + bhh1[j + 128], bih1[j + 192] + bhh1[j + 192]);
    for (int idx = tid; idx < 3 * HBUF; idx += 256) h0d[idx] = 0.0f;
    __syncthreads();

    float c0[4] = {0.f, 0.f, 0.f, 0.f};         // cell state for owned rows only
    float c1[4] = {0.f, 0.f, 0.f, 0.f};

    // gx prefetch for OWNED rows only
    ulonglong2 gx[4];
    #pragma unroll
    for (int r = 0; r < 4; r++)
        gx[r] = g_gx0[((size_t)base + rown + r) * H_ + j];   // t = 0

    for (int t = 0; t < T_; t++) {
        ulonglong2 gxn[4];
        if (t + 1 < T_) {
            #pragma unroll
            for (int r = 0; r < 4; r++)
                gxn[r] = g_gx0[((size_t)(t + 1) * B_ + base + rown + r) * H_ + j];
        }
        const float* h0r = h0d + (t & 1) * HBUF;         // prev-step h0
        float*       h0w = h0d + ((t & 1) ^ 1) * HBUF;   // this-step h0

        // ---------------- layer 0: partial = [gx0] + W_hh0[kh] . h0_prev ------
        // accum index o = 0..3 owned rows, 4..7 non-owned (to publish).
        // physical rows: owned = ro+kh*4+o ; non-owned = ro+(1-kh)*4+(o-4)
        ull aif[8], ago[8];
        #pragma unroll
        for (int r = 0; r < 4; r++) { aif[r] = gx[r].x; ago[r] = gx[r].y; }
        #pragma unroll
        for (int r = 4; r < 8; r++) { aif[r] = 0ull; ago[r] = 0ull; }

        #pragma unroll 4
        for (int i = 0; i < 32; i++) {
            int k = kb + i;
            ulonglong2 w  = W0p[k * 64 + j];                   // lane-contig LDS.128
            // hO = owned rows quad, hN = non-owned rows quad
            float4 hO = *(const float4*)&h0r[k * HP + rown];
            float4 hN = *(const float4*)&h0r[k * HP + (ro + 4 - kh * 4)];
            ull d0 = dupf(hO.x), d1 = dupf(hO.y), d2 = dupf(hO.z), d3 = dupf(hO.w);
            ull d4 = dupf(hN.x), d5 = dupf(hN.y), d6 = dupf(hN.z), d7 = dupf(hN.w);
            fma2(aif[0], w.x, d0); fma2(ago[0], w.y, d0);
            fma2(aif[1], w.x, d1); fma2(ago[1], w.y, d1);
            fma2(aif[2], w.x, d2); fma2(ago[2], w.y, d2);
            fma2(aif[3], w.x, d3); fma2(ago[3], w.y, d3);
            fma2(aif[4], w.x, d4); fma2(ago[4], w.y, d4);
            fma2(aif[5], w.x, d5); fma2(ago[5], w.y, d5);
            fma2(aif[6], w.x, d6); fma2(ago[6], w.y, d6);
            fma2(aif[7], w.x, d7); fma2(ago[7], w.y, d7);
        }
        // publish non-owned partials
        #pragma unroll
        for (int m = 0; m < 4; m++) {
            scr[(pubm + m)     * 128 + tl] = aif[4 + m];
            scr[(pubm + m + 4) * 128 + tl] = ago[4 + m];
        }
        __syncthreads();   // BAR1: partials visible; all h0r reads done
        {
            #pragma unroll
            for (int m = 0; m < 4; m++) {
                add2(aif[m], scr[(rdm + m)     * 128 + tl]);
                add2(ago[m], scr[(rdm + m + 4) * 128 + tl]);
            }
            float h0n[4];
            #pragma unroll
            for (int r = 0; r < 4; r++) {
                float i_ = sigf(lo32(aif[r])),  f_ = sigf(hi32(aif[r]));
                float g_ = tanhf_(lo32(ago[r])), o_ = sigf(hi32(ago[r]));
                c0[r]  = f_ * c0[r] + i_ * g_;
                h0n[r] = o_ * tanhf_(c0[r]);
            }
            *(float4*)&h0w[j * HP + rown] = make_float4(h0n[0], h0n[1], h0n[2], h0n[3]);
        }
        __syncthreads();   // BAR2: new h0 visible; scratch free for reuse

        // -------- layer 1: partial = [b1] + W_ih1[kh].h0_new + W_hh1[kh].h1 ---
        ull bif_[8], bgo_[8];
        #pragma unroll
        for (int r = 0; r < 4; r++) { bif_[r] = b1if; bgo_[r] = b1go; }
        #pragma unroll
        for (int r = 4; r < 8; r++) { bif_[r] = 0ull; bgo_[r] = 0ull; }

        #pragma unroll 2
        for (int i = 0; i < 32; i++) {
            int k = kb + i;
            ulonglong2 wi = W1ip[k * 64 + j];
            ulonglong2 wh = W1hp[k * 64 + j];
            float4 eO = *(const float4*)&h0w[k * HP + rown];
            float4 eN = *(const float4*)&h0w[k * HP + (ro + 4 - kh * 4)];
            float4 pO = *(const float4*)&h1d[k * HP + rown];
            float4 pN = *(const float4*)&h1d[k * HP + (ro + 4 - kh * 4)];
            ull e0 = dupf(eO.x), e1 = dupf(eO.y), e2 = dupf(eO.z), e3 = dupf(eO.w);
            ull e4 = dupf(eN.x), e5 = dupf(eN.y), e6 = dupf(eN.z), e7 = dupf(eN.w);
            fma2(bif_[0], wi.x, e0); fma2(bgo_[0], wi.y, e0);
            fma2(bif_[1], wi.x, e1); fma2(bgo_[1], wi.y, e1);
            fma2(bif_[2], wi.x, e2); fma2(bgo_[2], wi.y, e2);
            fma2(bif_[3], wi.x, e3); fma2(bgo_[3], wi.y, e3);
            fma2(bif_[4], wi.x, e4); fma2(bgo_[4], wi.y, e4);
            fma2(bif_[5], wi.x, e5); fma2(bgo_[5], wi.y, e5);
            fma2(bif_[6], wi.x, e6); fma2(bgo_[6], wi.y, e6);
            fma2(bif_[7], wi.x, e7); fma2(bgo_[7], wi.y, e7);
            ull p0 = dupf(pO.x), p1 = dupf(pO.y), p2 = dupf(pO.z), p3 = dupf(pO.w);
            ull p4 = dupf(pN.x), p5 = dupf(pN.y), p6 = dupf(pN.z), p7 = dupf(pN.w);
            fma2(bif_[0], wh.x, p0); fma2(bgo_[0], wh.y, p0);
            fma2(bif_[1], wh.x, p1); fma2(bgo_[1], wh.y, p1);
            fma2(bif_[2], wh.x, p2); fma2(bgo_[2], wh.y, p2);
            fma2(bif_[3], wh.x, p3); fma2(bgo_[3], wh.y, p3);
            fma2(bif_[4], wh.x, p4); fma2(bgo_[4], wh.y, p4);
            fma2(bif_[5], wh.x, p5); fma2(bgo_[5], wh.y, p5);
            fma2(bif_[6], wh.x, p6); fma2(bgo_[6], wh.y, p6);
            fma2(bif_[7], wh.x, p7); fma2(bgo_[7], wh.y, p7);
        }
        #pragma unroll
        for (int m = 0; m < 4; m++) {
            scr[(pubm + m)     * 128 + tl] = bif_[4 + m];
            scr[(pubm + m + 4) * 128 + tl] = bgo_[4 + m];
        }
        __syncthreads();   // BAR3: partials visible; all h1/h0w reads done
        {
            #pragma unroll
            for (int m = 0; m < 4; m++) {
                add2(bif_[m], scr[(rdm + m)     * 128 + tl]);
                add2(bgo_[m], scr[(rdm + m + 4) * 128 + tl]);
            }
            float h1n[4];
            #pragma unroll
            for (int r = 0; r < 4; r++) {
                float i_ = sigf(lo32(bif_[r])),  f_ = sigf(hi32(bif_[r]));
                float g_ = tanhf_(lo32(bgo_[r])), o_ = sigf(hi32(bgo_[r]));
                c1[r]  = f_ * c1[r] + i_ * g_;
                h1n[r] = o_ * tanhf_(c1[r]);
            }
            *(float4*)&h1d[j * HP + rown] = make_float4(h1n[0], h1n[1], h1n[2], h1n[3]);
        }
        #pragma unroll
        for (int r = 0; r < 4; r++) gx[r] = gxn[r];
        __syncthreads();   // BAR4: new h1 visible; scratch free for next step
    }

    // ---------------- fc (64 -> 5) + softmax on final h1 ----------------
    if (tid < 16) {
        const int row = tid;
        const int b   = base + row;
        float lgt[5];
        float mx = -1e30f;
        #pragma unroll
        for (int o = 0; o < 5; o++) {
            float s = bfc[o];
            #pragma unroll 8
            for (int k = 0; k < 64; k++)
                s += h1d[k * HP + row] * Wfc[o * 64 + k];
            lgt[o] = s;
            mx = fmaxf(mx, s);
        }
        float e[5], den = 0.0f;
        #pragma unroll
        for (int o = 0; o < 5; o++) { e[o] = __expf(lgt[o] - mx); den += e[o]; }
        float inv = __fdividef(1.0f, den);
        #pragma unroll
        for (int o = 0; o < 5; o++) out[(size_t)b * 5 + o] = e[o] * inv;
    }
}

// ============================================================================
extern "C" void kernel_launch(void* const* d_in, const int* in_sizes, int n_in,
                              void* d_out, int out_size)
{
    const float* x    = (const float*)d_in[0];
    const float* Wih0 = (const float*)d_in[1];
    const float* Whh0 = (const float*)d_in[2];
    const float* bih0 = (const float*)d_in[3];
    const float* bhh0 = (const float*)d_in[4];
    const float* Wih1 = (const float*)d_in[5];
    const float* Whh1 = (const float*)d_in[6];
    const float* bih1 = (const float*)d_in[7];
    const float* bhh1 = (const float*)d_in[8];
    const float* Wfc  = (const float*)d_in[9];
    const float* bfc  = (const float*)d_in[10];
    float* out = (float*)d_out;

    cudaFuncSetAttribute(gx0_prepass, cudaFuncAttributeMaxDynamicSharedMemorySize, PP_SMEM);
    cudaFuncSetAttribute(lstm_rec,    cudaFuncAttributeMaxDynamicSharedMemorySize, SMEM_REC);

    gx0_prepass<<<(B_ * T_) / 32, 256, PP_SMEM>>>(x, Wih0, bih0, bhh0);
    lstm_rec<<<B_ / 16, 256, SMEM_REC>>>(Whh0, Wih1, Whh1, bih1, bhh1, Wfc, bfc, out);
}

// round 15
// speedup vs baseline: 1.1020x; 1.1020x over previous
#include <cuda_runtime.h>
#include <cstdint>
#include <cstddef>

#define B_  2048
#define T_  256
#define D_  42
#define H_  64

typedef unsigned long long ull;

// 512MB scratch: gate-packed layer-0 preactivations, {(i,f),(g,o)} per (t,b,j)
__device__ ulonglong2 g_gx0[(size_t)B_ * T_ * H_];

// ---------------------------------------------------------------- helpers ---
__device__ __forceinline__ void fma2(ull& d, ull a, ull b) {
    asm("fma.rn.f32x2 %0, %1, %2, %0;" : "+l"(d) : "l"(a), "l"(b));
}
__device__ __forceinline__ void add2(ull& d, ull a) {
    asm("add.rn.f32x2 %0, %0, %1;" : "+l"(d) : "l"(a));
}
__device__ __forceinline__ ull dupf(float v) {
    unsigned r = __float_as_uint(v);
    ull d; asm("mov.b64 %0, {%1, %1};" : "=l"(d) : "r"(r));
    return d;
}
__device__ __forceinline__ ull pack2(float lo, float hi) {
    return (ull)__float_as_uint(lo) | ((ull)__float_as_uint(hi) << 32);
}
__device__ __forceinline__ float lo32(ull u) { return __uint_as_float((unsigned)u); }
__device__ __forceinline__ float hi32(ull u) { return __uint_as_float((unsigned)(u >> 32)); }
__device__ __forceinline__ float sigf(float x)   { return __fdividef(1.0f, 1.0f + __expf(-x)); }
__device__ __forceinline__ float tanhf_(float x) { float e = __expf(2.0f * x); return 1.0f - __fdividef(2.0f, e + 1.0f); }

// ============================================================================
// Fused kernel: 128 blocks x 16 batch rows, 256 threads (8 warps).
//
// PHASE A (prepass, fused): block computes gx0 for its OWN 16 rows x 256 t
//   using W_ih0 staged in the W0p smem region (not yet needed by phase B).
//   No cross-block dependency -> no global barrier, no second kernel.
// PHASE B (recurrence): exactly the proven R10 kernel.
//   Warp bits: jhi = w&1 (j = jhi*32+lane), rq = (w>>1)&1 (8 rows), kh = w>>2
//   (k-half). kh1 publishes partials via smem scratch; kh0 merges + cell
//   updates. Lane-contig LDS.128 weights, warp-uniform float4 h broadcasts,
//   gate-packed FFMA2 with register h-dups, double-buffered h0, 4 bar/step.
// ============================================================================
#define HP        20                                     // h pitch in floats
#define HBUF      (64 * HP)                              // 1280 floats / buffer
#define SCR_OFF   (3 * 64 * 64 * 16 + 3 * HBUF * 4)      // 211968
#define SMEM_REC  (SCR_OFF + 16 * 128 * 8)               // + 16384 = 228352 B
#define TCH       8                                      // t-chunk for phase A

__global__ void __launch_bounds__(256, 1)
lstm_fused(const float* __restrict__ x,
           const float* __restrict__ Wih0,
           const float* __restrict__ bih0,
           const float* __restrict__ bhh0,
           const float* __restrict__ Whh0,
           const float* __restrict__ Wih1,
           const float* __restrict__ Whh1,
           const float* __restrict__ bih1,
           const float* __restrict__ bhh1,
           const float* __restrict__ Wfc,
           const float* __restrict__ bfc,
           float* __restrict__ out)
{
    extern __shared__ char sm[];
    ulonglong2* W0p  = (ulonglong2*)sm;          // [k*64 + j], 64KB
    ulonglong2* W1ip = W0p  + 64 * 64;           // 64KB
    ulonglong2* W1hp = W1ip + 64 * 64;           // 64KB
    float*      h0d  = (float*)(W1hp + 64 * 64); // 2 buffers of HBUF
    float*      h1d  = h0d + 2 * HBUF;           // 1 buffer
    ull*        scr  = (ull*)(sm + SCR_OFF);     // [16][128] partials

    const int tid  = threadIdx.x;
    const int base = blockIdx.x * 16;

    // ======================= PHASE A: fused prepass =======================
    {
        ulonglong2* Wsh  = W0p;                  // reuse weight region (43KB)
        float*      xbuf = h0d;                  // 16*TCH*42 floats = 21504B

        const int j    = tid & 63;
        const int slot = tid >> 6;               // 0..3 -> rows slot*4..+3

        for (int idx = tid; idx < D_ * H_; idx += 256) {
            int d = idx >> 6, jj = idx & 63;
            Wsh[idx] = make_ulonglong2(
                pack2(Wih0[(jj      ) * D_ + d], Wih0[(jj +  64) * D_ + d]),
                pack2(Wih0[(jj + 128) * D_ + d], Wih0[(jj + 192) * D_ + d]));
        }
        const ull bifA = pack2(bih0[j      ] + bhh0[j      ], bih0[j +  64] + bhh0[j +  64]);
        const ull bgoA = pack2(bih0[j + 128] + bhh0[j + 128], bih0[j + 192] + bhh0[j + 192]);

        for (int tc = 0; tc < T_ / TCH; tc++) {
            __syncthreads();   // previous chunk's xbuf reads done (and W pack on tc=0)
            for (int idx = tid; idx < 16 * TCH * D_; idx += 256) {
                int row = idx / (TCH * D_);
                int rem = idx - row * (TCH * D_);
                int tt  = rem / D_;
                int d   = rem - tt * D_;
                xbuf[idx] = x[((size_t)(base + row) * T_ + (tc * TCH + tt)) * D_ + d];
            }
            __syncthreads();   // chunk staged

            for (int tt = 0; tt < TCH; tt++) {
                ull aif[4], ago[4];
                #pragma unroll
                for (int r = 0; r < 4; r++) { aif[r] = bifA; ago[r] = bgoA; }

                const float* xr = &xbuf[(slot * 4) * (TCH * D_) + tt * D_];
                #pragma unroll 6
                for (int d = 0; d < D_; d++) {
                    ulonglong2 w = Wsh[d * 64 + j];
                    ull x0 = dupf(xr[d]);
                    ull x1 = dupf(xr[TCH * D_ + d]);
                    ull x2 = dupf(xr[2 * TCH * D_ + d]);
                    ull x3 = dupf(xr[3 * TCH * D_ + d]);
                    fma2(aif[0], w.x, x0); fma2(ago[0], w.y, x0);
                    fma2(aif[1], w.x, x1); fma2(ago[1], w.y, x1);
                    fma2(aif[2], w.x, x2); fma2(ago[2], w.y, x2);
                    fma2(aif[3], w.x, x3); fma2(ago[3], w.y, x3);
                }
                size_t t = tc * TCH + tt;
                #pragma unroll
                for (int r = 0; r < 4; r++)
                    g_gx0[(t * B_ + base + slot * 4 + r) * H_ + j] =
                        make_ulonglong2(aif[r], ago[r]);
            }
        }
        __syncthreads();       // phase A fully done before weight overwrite
    }

    // ======================= PHASE B: recurrence (R10) =====================
    const int lane = tid & 31;
    const int wrp  = tid >> 5;                   // 0..7
    const int jhi  = wrp & 1;
    const int rq   = (wrp >> 1) & 1;             // 0..1 (8 rows each)
    const int kh   = wrp >> 2;                   // 0..1 (32 k each)
    const int j    = jhi * 32 + lane;
    const int ro   = rq * 8;
    const int kb   = kh * 32;                    // k-range start

    for (int idx = tid; idx < 64 * 64; idx += 256) {
        int k = idx >> 6, jj = idx & 63;
        W0p[idx]  = make_ulonglong2(
            pack2(Whh0[(jj      ) * 64 + k], Whh0[(jj +  64) * 64 + k]),
            pack2(Whh0[(jj + 128) * 64 + k], Whh0[(jj + 192) * 64 + k]));
        W1ip[idx] = make_ulonglong2(
            pack2(Wih1[(jj      ) * 64 + k], Wih1[(jj +  64) * 64 + k]),
            pack2(Wih1[(jj + 128) * 64 + k], Wih1[(jj + 192) * 64 + k]));
        W1hp[idx] = make_ulonglong2(
            pack2(Whh1[(jj      ) * 64 + k], Whh1[(jj +  64) * 64 + k]),
            pack2(Whh1[(jj + 128) * 64 + k], Whh1[(jj + 192) * 64 + k]));
    }
    const ull b1if = pack2(bih1[j      ] + bhh1[j      ], bih1[j +  64] + bhh1[j +  64]);
    const ull b1go = pack2(bih1[j + 128] + bhh1[j + 128], bih1[j + 192] + bhh1[j + 192]);
    for (int idx = tid; idx < 3 * HBUF; idx += 256) h0d[idx] = 0.0f;
    __syncthreads();

    float c0[8] = {0.f,0.f,0.f,0.f,0.f,0.f,0.f,0.f};
    float c1[8] = {0.f,0.f,0.f,0.f,0.f,0.f,0.f,0.f};

    // gx prefetch: kh0 threads only (they own the accumulator init)
    ulonglong2 gx[8];
    if (kh == 0) {
        #pragma unroll
        for (int r = 0; r < 8; r++)
            gx[r] = g_gx0[((size_t)base + ro + r) * H_ + j];     // t = 0
    }

    for (int t = 0; t < T_; t++) {
        ulonglong2 gxn[8];
        if (kh == 0 && t + 1 < T_) {
            #pragma unroll
            for (int r = 0; r < 8; r++)
                gxn[r] = g_gx0[((size_t)(t + 1) * B_ + base + ro + r) * H_ + j];
        }
        const float* h0r = h0d + (t & 1) * HBUF;         // prev-step h0
        float*       h0w = h0d + ((t & 1) ^ 1) * HBUF;   // this-step h0

        // ---------------- layer 0: partial = [gx0] + W_hh0[kh] . h0_prev ------
        ull aif[8], ago[8];
        if (kh == 0) {
            #pragma unroll
            for (int r = 0; r < 8; r++) { aif[r] = gx[r].x; ago[r] = gx[r].y; }
        } else {
            #pragma unroll
            for (int r = 0; r < 8; r++) { aif[r] = 0ull; ago[r] = 0ull; }
        }
        #pragma unroll 4
        for (int i = 0; i < 32; i++) {
            int k = kb + i;
            ulonglong2 w  = W0p[k * 64 + j];                   // lane-contig LDS.128
            float4 hA = *(const float4*)&h0r[k * HP + ro];     // warp-uniform bcast
            float4 hB = *(const float4*)&h0r[k * HP + ro + 4];
            ull d0 = dupf(hA.x), d1 = dupf(hA.y), d2 = dupf(hA.z), d3 = dupf(hA.w);
            ull d4 = dupf(hB.x), d5 = dupf(hB.y), d6 = dupf(hB.z), d7 = dupf(hB.w);
            fma2(aif[0], w.x, d0); fma2(ago[0], w.y, d0);
            fma2(aif[1], w.x, d1); fma2(ago[1], w.y, d1);
            fma2(aif[2], w.x, d2); fma2(ago[2], w.y, d2);
            fma2(aif[3], w.x, d3); fma2(ago[3], w.y, d3);
            fma2(aif[4], w.x, d4); fma2(ago[4], w.y, d4);
            fma2(aif[5], w.x, d5); fma2(ago[5], w.y, d5);
            fma2(aif[6], w.x, d6); fma2(ago[6], w.y, d6);
            fma2(aif[7], w.x, d7); fma2(ago[7], w.y, d7);
        }
        if (kh == 1) {                                    // publish partials
            int tl = tid & 127;
            #pragma unroll
            for (int m = 0; m < 8; m++) {
                scr[m * 128 + tl]       = aif[m];
                scr[(m + 8) * 128 + tl] = ago[m];
            }
        }
        __syncthreads();   // BAR1: partials visible; all h0r reads done
        if (kh == 0) {
            #pragma unroll
            for (int m = 0; m < 8; m++) {
                add2(aif[m], scr[m * 128 + tid]);
                add2(ago[m], scr[(m + 8) * 128 + tid]);
            }
            float h0n[8];
            #pragma unroll
            for (int r = 0; r < 8; r++) {
                float i_ = sigf(lo32(aif[r])),  f_ = sigf(hi32(aif[r]));
                float g_ = tanhf_(lo32(ago[r])), o_ = sigf(hi32(ago[r]));
                c0[r]  = f_ * c0[r] + i_ * g_;
                h0n[r] = o_ * tanhf_(c0[r]);
            }
            *(float4*)&h0w[j * HP + ro]     = make_float4(h0n[0], h0n[1], h0n[2], h0n[3]);
            *(float4*)&h0w[j * HP + ro + 4] = make_float4(h0n[4], h0n[5], h0n[6], h0n[7]);
        }
        __syncthreads();   // BAR2: new h0 visible; scratch free for reuse

        // -------- layer 1: partial = [b1] + W_ih1[kh].h0_new + W_hh1[kh].h1 ---
        ull bif_[8], bgo_[8];
        if (kh == 0) {
            #pragma unroll
            for (int r = 0; r < 8; r++) { bif_[r] = b1if; bgo_[r] = b1go; }
        } else {
            #pragma unroll
            for (int r = 0; r < 8; r++) { bif_[r] = 0ull; bgo_[r] = 0ull; }
        }
        #pragma unroll 2
        for (int i = 0; i < 32; i++) {
            int k = kb + i;
            ulonglong2 wi = W1ip[k * 64 + j];
            ulonglong2 wh = W1hp[k * 64 + j];
            float4 eA = *(const float4*)&h0w[k * HP + ro];
            float4 eB = *(const float4*)&h0w[k * HP + ro + 4];
            float4 pA = *(const float4*)&h1d[k * HP + ro];
            float4 pB = *(const float4*)&h1d[k * HP + ro + 4];
            ull e0 = dupf(eA.x), e1 = dupf(eA.y), e2 = dupf(eA.z), e3 = dupf(eA.w);
            ull e4 = dupf(eB.x), e5 = dupf(eB.y), e6 = dupf(eB.z), e7 = dupf(eB.w);
            fma2(bif_[0], wi.x, e0); fma2(bgo_[0], wi.y, e0);
            fma2(bif_[1], wi.x, e1); fma2(bgo_[1], wi.y, e1);
            fma2(bif_[2], wi.x, e2); fma2(bgo_[2], wi.y, e2);
            fma2(bif_[3], wi.x, e3); fma2(bgo_[3], wi.y, e3);
            fma2(bif_[4], wi.x, e4); fma2(bgo_[4], wi.y, e4);
            fma2(bif_[5], wi.x, e5); fma2(bgo_[5], wi.y, e5);
            fma2(bif_[6], wi.x, e6); fma2(bgo_[6], wi.y, e6);
            fma2(bif_[7], wi.x, e7); fma2(bgo_[7], wi.y, e7);
            ull p0 = dupf(pA.x), p1 = dupf(pA.y), p2 = dupf(pA.z), p3 = dupf(pA.w);
            ull p4 = dupf(pB.x), p5 = dupf(pB.y), p6 = dupf(pB.z), p7 = dupf(pB.w);
            fma2(bif_[0], wh.x, p0); fma2(bgo_[0], wh.y, p0);
            fma2(bif_[1], wh.x, p1); fma2(bgo_[1], wh.y, p1);
            fma2(bif_[2], wh.x, p2); fma2(bgo_[2], wh.y, p2);
            fma2(bif_[3], wh.x, p3); fma2(bgo_[3], wh.y, p3);
            fma2(bif_[4], wh.x, p4); fma2(bgo_[4], wh.y, p4);
            fma2(bif_[5], wh.x, p5); fma2(bgo_[5], wh.y, p5);
            fma2(bif_[6], wh.x, p6); fma2(bgo_[6], wh.y, p6);
            fma2(bif_[7], wh.x, p7); fma2(bgo_[7], wh.y, p7);
        }
        if (kh == 1) {
            int tl = tid & 127;
            #pragma unroll
            for (int m = 0; m < 8; m++) {
                scr[m * 128 + tl]       = bif_[m];
                scr[(m + 8) * 128 + tl] = bgo_[m];
            }
        }
        __syncthreads();   // BAR3: partials visible; all h1/h0w reads done
        if (kh == 0) {
            #pragma unroll
            for (int m = 0; m < 8; m++) {
                add2(bif_[m], scr[m * 128 + tid]);
                add2(bgo_[m], scr[(m + 8) * 128 + tid]);
            }
            float h1n[8];
            #pragma unroll
            for (int r = 0; r < 8; r++) {
                float i_ = sigf(lo32(bif_[r])),  f_ = sigf(hi32(bif_[r]));
                float g_ = tanhf_(lo32(bgo_[r])), o_ = sigf(hi32(bgo_[r]));
                c1[r]  = f_ * c1[r] + i_ * g_;
                h1n[r] = o_ * tanhf_(c1[r]);
            }
            *(float4*)&h1d[j * HP + ro]     = make_float4(h1n[0], h1n[1], h1n[2], h1n[3]);
            *(float4*)&h1d[j * HP + ro + 4] = make_float4(h1n[4], h1n[5], h1n[6], h1n[7]);
            #pragma unroll
            for (int r = 0; r < 8; r++) gx[r] = gxn[r];
        }
        __syncthreads();   // BAR4: new h1 visible; scratch free for next step
    }

    // ---------------- fc (64 -> 5) + softmax on final h1 ----------------
    if (tid < 16) {
        const int row = tid;
        const int b   = base + row;
        float lgt[5];
        float mx = -1e30f;
        #pragma unroll
        for (int o = 0; o < 5; o++) {
            float s = bfc[o];
            #pragma unroll 8
            for (int k = 0; k < 64; k++)
                s += h1d[k * HP + row] * Wfc[o * 64 + k];
            lgt[o] = s;
            mx = fmaxf(mx, s);
        }
        float e[5], den = 0.0f;
        #pragma unroll
        for (int o = 0; o < 5; o++) { e[o] = __expf(lgt[o] - mx); den += e[o]; }
        float inv = __fdividef(1.0f, den);
        #pragma unroll
        for (int o = 0; o < 5; o++) out[(size_t)b * 5 + o] = e[o] * inv;
    }
}

// ============================================================================
extern "C" void kernel_launch(void* const* d_in, const int* in_sizes, int n_in,
                              void* d_out, int out_size)
{
    const float* x    = (const float*)d_in[0];
    const float* Wih0 = (const float*)d_in[1];
    const float* Whh0 = (const float*)d_in[2];
    const float* bih0 = (const float*)d_in[3];
    const float* bhh0 = (const float*)d_in[4];
    const float* Wih1 = (const float*)d_in[5];
    const float* Whh1 = (const float*)d_in[6];
    const float* bih1 = (const float*)d_in[7];
    const float* bhh1 = (const float*)d_in[8];
    const float* Wfc  = (const float*)d_in[9];
    const float* bfc  = (const float*)d_in[10];
    float* out = (float*)d_out;

    cudaFuncSetAttribute(lstm_fused, cudaFuncAttributeMaxDynamicSharedMemorySize, SMEM_REC);

    lstm_fused<<<B_ / 16, 256, SMEM_REC>>>(x, Wih0, bih0, bhh0,
                                           Whh0, Wih1, Whh1, bih1, bhh1,
                                           Wfc, bfc, out);
}